// round 3
// baseline (speedup 1.0000x reference)
#include <cuda_runtime.h>
#include <math.h>
#include <stdint.h>

// Problem dims
#define LL  4
#define BB  2
#define SSq 512
#define MMm 512
#define DDd 1024
#define HHh 16
#define DKk 64
#define FFf 4096
#define TTt (SSq + MMm)   // 1024

// ---------------- scratch (device globals; no allocation allowed) ----------------
__device__ float g_pos[TTt * DDd];
__device__ float g_kv [BB * TTt * DDd];
__device__ float g_q  [BB * SSq * DDd];
__device__ float g_k  [BB * TTt * DDd];
__device__ float g_v  [BB * TTt * DDd];
__device__ float g_r  [TTt * DDd];
__device__ float g_attn[BB * SSq * DDd];
__device__ float g_tmp [BB * SSq * DDd];
__device__ float g_ff  [BB * SSq * FFf];
__device__ float g_h   [BB * SSq * DDd];
__device__ float g_h1  [BB * SSq * DDd];

// ---------------- PTX helpers ----------------
__device__ __forceinline__ uint32_t f2tf32(float f) {
    uint32_t u;
    asm("cvt.rna.tf32.f32 %0, %1;" : "=r"(u) : "f"(f));
    return u;
}
__device__ __forceinline__ void mma_tf32(float c[4], const uint32_t a[4], const uint32_t b[2]) {
    asm volatile(
        "mma.sync.aligned.m16n8k8.row.col.f32.tf32.tf32.f32 "
        "{%0,%1,%2,%3},{%4,%5,%6,%7},{%8,%9},{%0,%1,%2,%3};"
        : "+f"(c[0]), "+f"(c[1]), "+f"(c[2]), "+f"(c[3])
        : "r"(a[0]), "r"(a[1]), "r"(a[2]), "r"(a[3]), "r"(b[0]), "r"(b[1]));
}

// ---------------- positional encodings ----------------
__global__ void pos_kernel(float* __restrict__ pos)
{
    int idx = blockIdx.x * blockDim.x + threadIdx.x;
    if (idx >= TTt * DDd) return;
    int t = idx / DDd, d = idx % DDd;
    int j = (d < DDd / 2) ? d : d - DDd / 2;
    double invf = exp(((double)(-2 * j) / (double)DDd) * 9.210340371976184); // ln 1e4
    double ang  = (double)(TTt - 1 - t) * invf;
    double kk   = floor(ang * 0.15915494309189535);      // / 2pi
    float a = (float)(ang - kk * 6.283185307179586);
    pos[idx] = (d < DDd / 2) ? sinf(a) : cosf(a);
}

// ---------------- concat(memory[l], h) -> kv ----------------
__global__ void concat_kernel(float* __restrict__ kv, const float* __restrict__ mem,
                              const float* __restrict__ h)
{
    int idx = blockIdx.x * blockDim.x + threadIdx.x;
    if (idx >= BB * TTt * DDd) return;
    int d = idx % DDd;
    int t = (idx / DDd) % TTt;
    int b = idx / (DDd * TTt);
    kv[idx] = (t < MMm) ? mem[((size_t)b * MMm + t) * DDd + d]
                        : h[((size_t)b * SSq + (t - MMm)) * DDd + d];
}

// ======================================================================
// GEMM core: C[M,N] = alpha*A[M,K]@B[K,N] (+bias)(+relu)
// BM=128, BN=NWN*32, BK=16, 256 threads. tf32 converted once at smem store.
// ======================================================================
template<int NWN>
__device__ __forceinline__ void gemm_core(
    const float* __restrict__ A, const float* __restrict__ B, float* __restrict__ C,
    int N, int K, float alpha, const float* __restrict__ bias, int relu,
    int bx, int by)
{
    constexpr int BN = NWN * 32;
    constexpr int NWM = 8 / NWN;
    constexpr int WM = 128 / NWM;     // warp m extent
    constexpr int MT = WM / 16;       // m16 tiles per warp
    constexpr int BPITCH = BN + 8;
    constexpr int NB_CH = (BN * 16) / 1024;   // float4 B chunks per thread (2 or 1)

    __shared__ uint32_t As[2][128][20];
    __shared__ uint32_t Bs[2][16][BPITCH];

    int tid = threadIdx.x, lane = tid & 31, warp = tid >> 5;
    int g = lane >> 2, tg = lane & 3;
    int warp_m = warp % NWM, warp_n = warp / NWM;
    int wm = warp_m * WM, wn = warp_n * 32;

    const float* Ag = A + (size_t)by * 128 * K;
    const float* Bg = B + (size_t)bx * BN;

    float acc[MT][4][4];
#pragma unroll
    for (int mt = 0; mt < MT; mt++)
#pragma unroll
        for (int nt = 0; nt < 4; nt++)
#pragma unroll
            for (int i = 0; i < 4; i++) acc[mt][nt][i] = 0.f;

    // loader mappings
    int ar[2], ak[2];
#pragma unroll
    for (int j = 0; j < 2; j++) {
        int c = tid + j * 256;
        ar[j] = c >> 2; ak[j] = (c & 3) * 4;
    }
    int bk[2], bn[2];
#pragma unroll
    for (int j = 0; j < NB_CH; j++) {
        int c = tid + j * 256;
        if (BN == 128) { bk[j] = c >> 5; bn[j] = (c & 31) * 4; }
        else           { bk[j] = c >> 4; bn[j] = (c & 15) * 4; }
    }

    int nk = K / 16;
    float4 sA[2], sB[2];

    // prologue loads (tile 0)
#pragma unroll
    for (int j = 0; j < 2; j++)
        sA[j] = *(const float4*)(Ag + (size_t)ar[j] * K + ak[j]);
#pragma unroll
    for (int j = 0; j < NB_CH; j++)
        sB[j] = *(const float4*)(Bg + (size_t)bk[j] * N + bn[j]);
    // store tile 0 (convert)
#pragma unroll
    for (int j = 0; j < 2; j++) {
        uint4 u = make_uint4(f2tf32(sA[j].x), f2tf32(sA[j].y), f2tf32(sA[j].z), f2tf32(sA[j].w));
        *(uint4*)&As[0][ar[j]][ak[j]] = u;
    }
#pragma unroll
    for (int j = 0; j < NB_CH; j++) {
        uint4 u = make_uint4(f2tf32(sB[j].x), f2tf32(sB[j].y), f2tf32(sB[j].z), f2tf32(sB[j].w));
        *(uint4*)&Bs[0][bk[j]][bn[j]] = u;
    }
    __syncthreads();

    for (int kt = 0; kt < nk; kt++) {
        int buf = kt & 1;
        bool more = (kt + 1 < nk);
        if (more) {
#pragma unroll
            for (int j = 0; j < 2; j++)
                sA[j] = *(const float4*)(Ag + (size_t)ar[j] * K + (kt + 1) * 16 + ak[j]);
#pragma unroll
            for (int j = 0; j < NB_CH; j++)
                sB[j] = *(const float4*)(Bg + (size_t)((kt + 1) * 16 + bk[j]) * N + bn[j]);
        }

#pragma unroll
        for (int ks = 0; ks < 2; ks++) {
            uint32_t af[MT][4], bf[4][2];
#pragma unroll
            for (int mt = 0; mt < MT; mt++) {
                int row = wm + mt * 16;
                af[mt][0] = As[buf][row + g][ks * 8 + tg];
                af[mt][1] = As[buf][row + g + 8][ks * 8 + tg];
                af[mt][2] = As[buf][row + g][ks * 8 + tg + 4];
                af[mt][3] = As[buf][row + g + 8][ks * 8 + tg + 4];
            }
#pragma unroll
            for (int nt = 0; nt < 4; nt++) {
                int col = wn + nt * 8 + g;
                bf[nt][0] = Bs[buf][ks * 8 + tg][col];
                bf[nt][1] = Bs[buf][ks * 8 + tg + 4][col];
            }
#pragma unroll
            for (int mt = 0; mt < MT; mt++)
#pragma unroll
                for (int nt = 0; nt < 4; nt++) mma_tf32(acc[mt][nt], af[mt], bf[nt]);
        }

        if (more) {
            int nb = buf ^ 1;
#pragma unroll
            for (int j = 0; j < 2; j++) {
                uint4 u = make_uint4(f2tf32(sA[j].x), f2tf32(sA[j].y), f2tf32(sA[j].z), f2tf32(sA[j].w));
                *(uint4*)&As[nb][ar[j]][ak[j]] = u;
            }
#pragma unroll
            for (int j = 0; j < NB_CH; j++) {
                uint4 u = make_uint4(f2tf32(sB[j].x), f2tf32(sB[j].y), f2tf32(sB[j].z), f2tf32(sB[j].w));
                *(uint4*)&Bs[nb][bk[j]][bn[j]] = u;
            }
            __syncthreads();
        }
    }

    // epilogue
#pragma unroll
    for (int mt = 0; mt < MT; mt++) {
#pragma unroll
        for (int nt = 0; nt < 4; nt++) {
            int row = by * 128 + wm + mt * 16 + g;
            int col = bx * BN + wn + nt * 8 + tg * 2;
            float bx0 = 0.f, bx1 = 0.f;
            if (bias) { bx0 = bias[col]; bx1 = bias[col + 1]; }
            float v0 = acc[mt][nt][0] * alpha + bx0;
            float v1 = acc[mt][nt][1] * alpha + bx1;
            float v2 = acc[mt][nt][2] * alpha + bx0;
            float v3 = acc[mt][nt][3] * alpha + bx1;
            if (relu) {
                v0 = fmaxf(v0, 0.f); v1 = fmaxf(v1, 0.f);
                v2 = fmaxf(v2, 0.f); v3 = fmaxf(v3, 0.f);
            }
            *(float2*)(C + (size_t)row * N + col)       = make_float2(v0, v1);
            *(float2*)(C + (size_t)(row + 8) * N + col) = make_float2(v2, v3);
        }
    }
}

template<int NWN>
__global__ void __launch_bounds__(256) tc_gemm_k(
    const float* __restrict__ A, const float* __restrict__ B, float* __restrict__ C,
    int N, int K, float alpha, const float* __restrict__ bias, int relu)
{
    gemm_core<NWN>(A, B, C, N, K, alpha, bias, relu, blockIdx.x, blockIdx.y);
}

// grouped q/k/v/r projections: z selects the gemm
__global__ void __launch_bounds__(256) grouped_qkvr(
    const float* __restrict__ hc, const float* __restrict__ kv, const float* __restrict__ pos,
    const float* __restrict__ Wq, const float* __restrict__ Wk,
    const float* __restrict__ Wv, const float* __restrict__ Wr,
    float* __restrict__ q, float* __restrict__ k, float* __restrict__ v, float* __restrict__ r)
{
    int z = blockIdx.z;
    const float* A; const float* B; float* C; int mb; float alpha = 1.f;
    if (z == 0)      { A = hc;  B = Wq; C = q; mb = (BB * SSq) / 128; alpha = 0.125f; }
    else if (z == 1) { A = kv;  B = Wk; C = k; mb = (BB * TTt) / 128; }
    else if (z == 2) { A = kv;  B = Wv; C = v; mb = (BB * TTt) / 128; }
    else             { A = pos; B = Wr; C = r; mb = TTt / 128; }
    if ((int)blockIdx.y >= mb) return;
    gemm_core<4>(A, B, C, DDd, DDd, alpha, nullptr, 0, blockIdx.x, blockIdx.y);
}

// ======================================================================
// Fused attention: content + rel (diagonal window) + mask + softmax + P@V
// CTA = 32 query rows of one (b,h). 256 threads, 8 warps.
// ======================================================================
#define SMT   32
#define TN    64
#define LPITCH 1028
#define QPITCH 68
#define WPITCH 100
#define SMEM_ATTN_FLOATS (SMT*LPITCH + 2*SMT*QPITCH + 64*QPITCH + 96*QPITCH + SMT*WPITCH)
#define SMEM_ATTN_BYTES  (SMEM_ATTN_FLOATS * 4)

__global__ void __launch_bounds__(256) fused_attn(
    const float* __restrict__ q, const float* __restrict__ k, const float* __restrict__ v,
    const float* __restrict__ r, const float* __restrict__ rwb, const float* __restrict__ rrb,
    float* __restrict__ attn)
{
    extern __shared__ float sm[];
    float* L       = sm;                          // [32][1028] logits -> P(tf32 bits)
    uint32_t* Qcb  = (uint32_t*)(L + SMT * LPITCH);       // [32][68]
    uint32_t* Qrb  = Qcb + SMT * QPITCH;                  // [32][68]
    uint32_t* Ktb  = Qrb + SMT * QPITCH;                  // [64][68] K tile / V tile
    uint32_t* Rwb  = Ktb + 64 * QPITCH;                   // [96][68]
    float* QRW     = (float*)(Rwb + 96 * QPITCH);         // [32][100]
    uint32_t* Lb   = (uint32_t*)L;

    int tid = threadIdx.x, lane = tid & 31, warp = tid >> 5;
    int g = lane >> 2, tg = lane & 3;
    int s0 = blockIdx.x * SMT;
    int b = blockIdx.y >> 4, h = blockIdx.y & 15;

    const float* qb = q + (size_t)b * SSq * DDd + h * DKk;
    const float* kb = k + (size_t)b * TTt * DDd + h * DKk;
    const float* vb = v + (size_t)b * TTt * DDd + h * DKk;
    const float* rb = r + h * DKk;
    const float* wbv = rwb + h * DKk;
    const float* rbv = rrb + h * DKk;

    // phase 1: Qc = q + rwb, Qr = q + rrb (tf32)
#pragma unroll
    for (int j = 0; j < 2; j++) {
        int c = tid + j * 256;
        int row = c >> 4, k0 = (c & 15) * 4;
        float4 qv = *(const float4*)(qb + (size_t)(s0 + row) * DDd + k0);
        float4 w4 = *(const float4*)(wbv + k0);
        float4 r4 = *(const float4*)(rbv + k0);
        Qcb[row * QPITCH + k0 + 0] = f2tf32(qv.x + w4.x);
        Qcb[row * QPITCH + k0 + 1] = f2tf32(qv.y + w4.y);
        Qcb[row * QPITCH + k0 + 2] = f2tf32(qv.z + w4.z);
        Qcb[row * QPITCH + k0 + 3] = f2tf32(qv.w + w4.w);
        Qrb[row * QPITCH + k0 + 0] = f2tf32(qv.x + r4.x);
        Qrb[row * QPITCH + k0 + 1] = f2tf32(qv.y + r4.y);
        Qrb[row * QPITCH + k0 + 2] = f2tf32(qv.z + r4.z);
        Qrb[row * QPITCH + k0 + 3] = f2tf32(qv.w + r4.w);
    }
    __syncthreads();

    int ntiles = (s0 + 543) / 64 + 1;   // last t-tile containing any valid t
    int wm2 = (warp & 1) * 16;
    int wn2 = (warp >> 1) * 16;
    int wn3 = (warp >> 1) * 24;

    // phase 2: logits
    for (int it = 0; it < ntiles; it++) {
        int t0 = it * TN;
        int jb = t0 - s0 + 480;
        // load K tile [64][64]
#pragma unroll
        for (int j = 0; j < 4; j++) {
            int c = tid + j * 256;
            int row = c >> 4, k0 = (c & 15) * 4;
            float4 kv4 = *(const float4*)(kb + (size_t)(t0 + row) * DDd + k0);
            Ktb[row * QPITCH + k0 + 0] = f2tf32(kv4.x);
            Ktb[row * QPITCH + k0 + 1] = f2tf32(kv4.y);
            Ktb[row * QPITCH + k0 + 2] = f2tf32(kv4.z);
            Ktb[row * QPITCH + k0 + 3] = f2tf32(kv4.w);
        }
        // load R window [96][64]
#pragma unroll
        for (int j = 0; j < 6; j++) {
            int c = tid + j * 256;
            int row = c >> 4, k0 = (c & 15) * 4;
            int jg = jb + row; if (jg > TTt - 1) jg = TTt - 1;
            float4 rv4 = *(const float4*)(rb + (size_t)jg * DDd + k0);
            Rwb[row * QPITCH + k0 + 0] = f2tf32(rv4.x);
            Rwb[row * QPITCH + k0 + 1] = f2tf32(rv4.y);
            Rwb[row * QPITCH + k0 + 2] = f2tf32(rv4.z);
            Rwb[row * QPITCH + k0 + 3] = f2tf32(rv4.w);
        }
        __syncthreads();

        float ca[2][4], ra[3][4];
#pragma unroll
        for (int nt = 0; nt < 2; nt++)
#pragma unroll
            for (int i = 0; i < 4; i++) ca[nt][i] = 0.f;
#pragma unroll
        for (int nt = 0; nt < 3; nt++)
#pragma unroll
            for (int i = 0; i < 4; i++) ra[nt][i] = 0.f;

#pragma unroll
        for (int k8 = 0; k8 < 64; k8 += 8) {
            uint32_t af[4], afr[4];
            af[0]  = Qcb[(wm2 + g) * QPITCH + k8 + tg];
            af[1]  = Qcb[(wm2 + g + 8) * QPITCH + k8 + tg];
            af[2]  = Qcb[(wm2 + g) * QPITCH + k8 + tg + 4];
            af[3]  = Qcb[(wm2 + g + 8) * QPITCH + k8 + tg + 4];
            afr[0] = Qrb[(wm2 + g) * QPITCH + k8 + tg];
            afr[1] = Qrb[(wm2 + g + 8) * QPITCH + k8 + tg];
            afr[2] = Qrb[(wm2 + g) * QPITCH + k8 + tg + 4];
            afr[3] = Qrb[(wm2 + g + 8) * QPITCH + k8 + tg + 4];
#pragma unroll
            for (int nt = 0; nt < 2; nt++) {
                uint32_t bf[2];
                int col = wn2 + nt * 8 + g;
                bf[0] = Ktb[col * QPITCH + k8 + tg];
                bf[1] = Ktb[col * QPITCH + k8 + tg + 4];
                mma_tf32(ca[nt], af, bf);
            }
#pragma unroll
            for (int nt = 0; nt < 3; nt++) {
                uint32_t bf[2];
                int col = wn3 + nt * 8 + g;
                bf[0] = Rwb[col * QPITCH + k8 + tg];
                bf[1] = Rwb[col * QPITCH + k8 + tg + 4];
                mma_tf32(ra[nt], afr, bf);
            }
        }
        // write rel window
#pragma unroll
        for (int nt = 0; nt < 3; nt++) {
            int r0 = wm2 + g, c0 = wn3 + nt * 8 + tg * 2;
            QRW[r0 * WPITCH + c0]       = ra[nt][0];
            QRW[r0 * WPITCH + c0 + 1]   = ra[nt][1];
            QRW[(r0 + 8) * WPITCH + c0]     = ra[nt][2];
            QRW[(r0 + 8) * WPITCH + c0 + 1] = ra[nt][3];
        }
        __syncthreads();
        // combine: L[s][t] = content + rel(shifted) or -1e30 (mask)
#pragma unroll
        for (int nt = 0; nt < 2; nt++) {
            int tts = wn2 + nt * 8 + tg * 2;
#pragma unroll
            for (int i = 0; i < 4; i++) {
                int si = wm2 + g + ((i >= 2) ? 8 : 0);
                int tt = tts + (i & 1);
                int t = t0 + tt, s = s0 + si;
                float out;
                if (t - s <= MMm)
                    out = ca[nt][i] + QRW[si * WPITCH + tt + (SMT - 1) - si];
                else
                    out = -1e30f;
                L[si * LPITCH + t] = out;
            }
        }
        __syncthreads();
    }

    // phase 3: softmax rows (width ntiles*64), write P as tf32 bits
    int tb = ntiles * TN;
    for (int rr = 0; rr < 4; rr++) {
        int row = warp * 4 + rr;
        float* lr = L + row * LPITCH;
        float m = -1e30f;
        for (int c = lane; c < tb; c += 32) m = fmaxf(m, lr[c]);
#pragma unroll
        for (int o = 16; o; o >>= 1) m = fmaxf(m, __shfl_xor_sync(0xffffffffu, m, o));
        float ssum = 0.f;
        for (int c = lane; c < tb; c += 32) {
            float e = __expf(lr[c] - m);
            lr[c] = e;
            ssum += e;
        }
#pragma unroll
        for (int o = 16; o; o >>= 1) ssum += __shfl_xor_sync(0xffffffffu, ssum, o);
        float inv = 1.f / ssum;
        for (int c = lane; c < tb; c += 32)
            ((uint32_t*)lr)[c] = f2tf32(lr[c] * inv);
    }
    __syncthreads();

    // phase 4: P @ V
    float oacc[2][4];
#pragma unroll
    for (int nt = 0; nt < 2; nt++)
#pragma unroll
        for (int i = 0; i < 4; i++) oacc[nt][i] = 0.f;

    for (int it = 0; it < ntiles; it++) {
        int t0 = it * TN;
#pragma unroll
        for (int j = 0; j < 4; j++) {
            int c = tid + j * 256;
            int row = c >> 4, k0 = (c & 15) * 4;
            float4 vv4 = *(const float4*)(vb + (size_t)(t0 + row) * DDd + k0);
            Ktb[row * QPITCH + k0 + 0] = f2tf32(vv4.x);
            Ktb[row * QPITCH + k0 + 1] = f2tf32(vv4.y);
            Ktb[row * QPITCH + k0 + 2] = f2tf32(vv4.z);
            Ktb[row * QPITCH + k0 + 3] = f2tf32(vv4.w);
        }
        __syncthreads();
#pragma unroll
        for (int k8 = 0; k8 < 64; k8 += 8) {
            uint32_t af[4];
            af[0] = Lb[(wm2 + g) * LPITCH + t0 + k8 + tg];
            af[1] = Lb[(wm2 + g + 8) * LPITCH + t0 + k8 + tg];
            af[2] = Lb[(wm2 + g) * LPITCH + t0 + k8 + tg + 4];
            af[3] = Lb[(wm2 + g + 8) * LPITCH + t0 + k8 + tg + 4];
#pragma unroll
            for (int nt = 0; nt < 2; nt++) {
                uint32_t bf[2];
                int col = wn2 + nt * 8 + g;
                bf[0] = Ktb[(k8 + tg) * QPITCH + col];
                bf[1] = Ktb[(k8 + tg + 4) * QPITCH + col];
                mma_tf32(oacc[nt], af, bf);
            }
        }
        __syncthreads();
    }

    // phase 5: write attn[b][s][h*64+dk]
    float* ob = attn + ((size_t)b * SSq + s0) * DDd + h * DKk;
#pragma unroll
    for (int nt = 0; nt < 2; nt++) {
        int r0 = wm2 + g, c0 = wn2 + nt * 8 + tg * 2;
        *(float2*)(ob + (size_t)r0 * DDd + c0)       = make_float2(oacc[nt][0], oacc[nt][1]);
        *(float2*)(ob + (size_t)(r0 + 8) * DDd + c0) = make_float2(oacc[nt][2], oacc[nt][3]);
    }
}

// ---------------- residual + LayerNorm ----------------
__global__ void ln_kernel(const float* __restrict__ x, const float* __restrict__ res,
                          const float* __restrict__ g, const float* __restrict__ b,
                          float* __restrict__ out)
{
    int row = blockIdx.x;          // over B*S
    const float* xr = x + (size_t)row * DDd;
    const float* rr = res + (size_t)row * DDd;
    __shared__ float redA[33], redB[33];
    int tid = threadIdx.x;

    float loc[4];
    float s1 = 0.f, s2 = 0.f;
#pragma unroll
    for (int i = 0; i < 4; i++) {
        int d = tid + i * 256;
        float v = xr[d] + rr[d];
        loc[i] = v;
        s1 += v;
        s2 += v * v;
    }
#pragma unroll
    for (int o = 16; o; o >>= 1) {
        s1 += __shfl_xor_sync(0xffffffffu, s1, o);
        s2 += __shfl_xor_sync(0xffffffffu, s2, o);
    }
    if ((tid & 31) == 0) { redA[tid >> 5] = s1; redB[tid >> 5] = s2; }
    __syncthreads();
    if (tid < 32) {
        float a = (tid < 8) ? redA[tid] : 0.f;
        float c = (tid < 8) ? redB[tid] : 0.f;
#pragma unroll
        for (int o = 4; o; o >>= 1) {
            a += __shfl_xor_sync(0xffffffffu, a, o);
            c += __shfl_xor_sync(0xffffffffu, c, o);
        }
        if (tid == 0) { redA[32] = a; redB[32] = c; }
    }
    __syncthreads();
    float mu  = redA[32] * (1.f / DDd);
    float var = redB[32] * (1.f / DDd) - mu * mu;
    float rstd = rsqrtf(var + 1e-5f);
#pragma unroll
    for (int i = 0; i < 4; i++) {
        int d = tid + i * 256;
        out[(size_t)row * DDd + d] = (loc[i] - mu) * rstd * g[d] + b[d];
    }
}

// ---------------- host-side orchestration ----------------
extern "C" void kernel_launch(void* const* d_in, const int* in_sizes, int n_in,
                              void* d_out, int out_size)
{
    const float* x      = (const float*)d_in[0];
    const float* memory = (const float*)d_in[1];
    const float* Wq  = (const float*)d_in[2];
    const float* Wk  = (const float*)d_in[3];
    const float* Wv  = (const float*)d_in[4];
    const float* Wr  = (const float*)d_in[5];
    const float* Wo  = (const float*)d_in[6];
    const float* rwb = (const float*)d_in[7];
    const float* rrb = (const float*)d_in[8];
    const float* ln1g = (const float*)d_in[9];
    const float* ln1b = (const float*)d_in[10];
    const float* ln2g = (const float*)d_in[11];
    const float* ln2b = (const float*)d_in[12];
    const float* W1  = (const float*)d_in[13];
    const float* b1  = (const float*)d_in[14];
    const float* W2  = (const float*)d_in[15];
    const float* b2  = (const float*)d_in[16];
    float* out = (float*)d_out;

    float *pos, *kv, *q, *k, *v, *r, *attn, *tmp, *ff, *h, *h1;
    cudaGetSymbolAddress((void**)&pos,  g_pos);
    cudaGetSymbolAddress((void**)&kv,   g_kv);
    cudaGetSymbolAddress((void**)&q,    g_q);
    cudaGetSymbolAddress((void**)&k,    g_k);
    cudaGetSymbolAddress((void**)&v,    g_v);
    cudaGetSymbolAddress((void**)&r,    g_r);
    cudaGetSymbolAddress((void**)&attn, g_attn);
    cudaGetSymbolAddress((void**)&tmp,  g_tmp);
    cudaGetSymbolAddress((void**)&ff,   g_ff);
    cudaGetSymbolAddress((void**)&h,    g_h);
    cudaGetSymbolAddress((void**)&h1,   g_h1);

    cudaFuncSetAttribute(fused_attn, cudaFuncAttributeMaxDynamicSharedMemorySize,
                         SMEM_ATTN_BYTES);

    pos_kernel<<<(TTt * DDd + 255) / 256, 256>>>(pos);

    const float* hcur = x;
    for (int l = 0; l < LL; l++) {
        concat_kernel<<<(BB * TTt * DDd + 255) / 256, 256>>>(
            kv, memory + (size_t)l * BB * MMm * DDd, hcur);

        // q/k/v/r in one grouped launch (384 working CTAs)
        dim3 gG(DDd / 128, (BB * TTt) / 128, 4);
        grouped_qkvr<<<gG, 256>>>(hcur, kv, pos,
                                  Wq + (size_t)l * DDd * DDd, Wk + (size_t)l * DDd * DDd,
                                  Wv + (size_t)l * DDd * DDd, Wr + (size_t)l * DDd * DDd,
                                  q, k, v, r);

        // fused attention
        dim3 gA(SSq / SMT, BB * HHh);
        fused_attn<<<gA, 256, SMEM_ATTN_BYTES>>>(
            q, k, v, r, rwb + (size_t)l * HHh * DKk, rrb + (size_t)l * HHh * DKk, attn);

        // output projection (BN=64 -> 128 blocks)
        dim3 gO(DDd / 64, (BB * SSq) / 128);
        tc_gemm_k<2><<<gO, 256>>>(attn, Wo + (size_t)l * DDd * DDd, tmp,
                                  DDd, DDd, 1.f, nullptr, 0);
        ln_kernel<<<BB * SSq, 256>>>(tmp, hcur, ln1g + l * DDd, ln1b + l * DDd, h1);

        // FFN
        dim3 gF1(FFf / 128, (BB * SSq) / 128);
        tc_gemm_k<4><<<gF1, 256>>>(h1, W1 + (size_t)l * DDd * FFf, ff,
                                   FFf, DDd, 1.f, b1 + l * FFf, 1);
        dim3 gF2(DDd / 64, (BB * SSq) / 128);
        tc_gemm_k<2><<<gF2, 256>>>(ff, W2 + (size_t)l * FFf * DDd, tmp,
                                   DDd, FFf, 1.f, b2 + l * DDd, 0);

        float* hout = (l == LL - 1) ? out : h;
        ln_kernel<<<BB * SSq, 256>>>(tmp, h1, ln2g + l * DDd, ln2b + l * DDd, hout);
        hcur = h;
    }
}